// round 9
// baseline (speedup 1.0000x reference)
#include <cuda_runtime.h>
#include <cstdint>

#define BATCH  64
#define HID    1024
#define VOCAB  4096
#define SEQ    256
#define NBLK   128
#define NTHR   512
#define CH     128                 // A-chunk width (cols of K)
#define NCH    (HID / CH)          // 8 chunks
#define SAPAD  132                 // padded row stride for sA

// ---------------------------------------------------------------------------
// Global scratch
// ---------------------------------------------------------------------------
__device__ float g_H[(SEQ + 1) * BATCH * HID];
__device__ float g_P[BATCH * HID];
__device__ unsigned g_bar_count = 0;
__device__ unsigned g_bar_gen   = 0;

// ---------------------------------------------------------------------------
// helpers
// ---------------------------------------------------------------------------
__device__ __forceinline__ float tf32r(float x) {
    unsigned u;
    asm("cvt.rna.tf32.f32 %0, %1;" : "=r"(u) : "f"(x));
    return __uint_as_float(u);
}

__device__ __forceinline__ void mma8(float (&c)[4], const float (&a)[4], float b0, float b1) {
    unsigned a0 = __float_as_uint(a[0]), a1 = __float_as_uint(a[1]);
    unsigned a2 = __float_as_uint(a[2]), a3 = __float_as_uint(a[3]);
    unsigned B0 = __float_as_uint(b0),  B1 = __float_as_uint(b1);
    asm volatile(
        "mma.sync.aligned.m16n8k8.row.col.f32.tf32.tf32.f32 "
        "{%0,%1,%2,%3}, {%4,%5,%6,%7}, {%8,%9}, {%0,%1,%2,%3};\n"
        : "+f"(c[0]), "+f"(c[1]), "+f"(c[2]), "+f"(c[3])
        : "r"(a0), "r"(a1), "r"(a2), "r"(a3), "r"(B0), "r"(B1));
}

__device__ __forceinline__ float sigmoidf_(float x) { return 1.f / (1.f + __expf(-x)); }

// Light release/acquire grid barrier: thread 0 only touches global; block-level
// ordering via __syncthreads (cooperative-groups grid.sync pattern).
__device__ __forceinline__ void gridbar() {
    __syncthreads();
    if (threadIdx.x == 0) {
        unsigned gen;
        asm volatile("ld.relaxed.gpu.global.u32 %0, [%1];"
                     : "=r"(gen) : "l"(&g_bar_gen) : "memory");
        unsigned old;
        asm volatile("atom.acq_rel.gpu.global.add.u32 %0, [%1], 1;"
                     : "=r"(old) : "l"(&g_bar_count) : "memory");
        if (old == NBLK - 1) {
            asm volatile("st.relaxed.gpu.global.u32 [%0], %1;"
                         :: "l"(&g_bar_count), "r"(0u) : "memory");
            asm volatile("st.release.gpu.global.u32 [%0], %1;"
                         :: "l"(&g_bar_gen), "r"(gen + 1) : "memory");
        } else {
            unsigned cur;
            do {
                asm volatile("ld.acquire.gpu.global.u32 %0, [%1];"
                             : "=r"(cur) : "l"(&g_bar_gen) : "memory");
            } while (cur == gen);
        }
    }
    __syncthreads();
}

// ---------------------------------------------------------------------------
// MMA phase (R6-proven): acc[NT][4] = A(src)[64x1024] * W-slab(sW fragments)
//   wid = mt*4 + kq ; mt -> rows [16mt,16mt+16), kq -> K-quarter of chunk.
//   Double-buffered smem staging; LDG of chunk ch+1 overlaps MMA on chunk ch.
// ---------------------------------------------------------------------------
template<int NT>
__device__ __forceinline__ void mma_phase(
    const float* __restrict__ src,
    const float* __restrict__ sW,
    float* __restrict__ sA,
    float (&acc)[NT][4],
    int tid, int lane, int mt, int kq, int gid, int tg)
{
#pragma unroll
    for (int nt = 0; nt < NT; ++nt)
#pragma unroll
        for (int e = 0; e < 4; ++e) acc[nt][e] = 0.f;

    {
        float4 ra[4];
#pragma unroll
        for (int j = 0; j < 4; ++j) {
            int flat = j * NTHR + tid;
            int row = flat >> 5, kw = flat & 31;
            ra[j] = __ldcg(reinterpret_cast<const float4*>(src + (size_t)row * HID + kw * 4));
        }
#pragma unroll
        for (int j = 0; j < 4; ++j) {
            int flat = j * NTHR + tid;
            int row = flat >> 5, kw = flat & 31;
            float4 v;
            v.x = tf32r(ra[j].x); v.y = tf32r(ra[j].y);
            v.z = tf32r(ra[j].z); v.w = tf32r(ra[j].w);
            *reinterpret_cast<float4*>(sA + row * SAPAD + kw * 4) = v;
        }
    }
    __syncthreads();

    for (int ch = 0; ch < NCH; ++ch) {
        float4 rn[4];
        if (ch + 1 < NCH) {
#pragma unroll
            for (int j = 0; j < 4; ++j) {
                int flat = j * NTHR + tid;
                int row = flat >> 5, kw = flat & 31;
                rn[j] = __ldcg(reinterpret_cast<const float4*>(
                    src + (size_t)row * HID + (ch + 1) * CH + kw * 4));
            }
        }

        const float* aBase = sA + (ch & 1) * (64 * SAPAD) + (mt * 16 + gid) * SAPAD;
#pragma unroll
        for (int i = 0; i < 4; ++i) {
            int k8l = kq * 4 + i;
            int kb  = k8l * 8;
            float a[4];
            a[0] = aBase[kb + tg];
            a[1] = aBase[8 * SAPAD + kb + tg];
            a[2] = aBase[kb + 4 + tg];
            a[3] = aBase[8 * SAPAD + kb + 4 + tg];
            int k8g = ch * 16 + k8l;
#pragma unroll
            for (int nt = 0; nt < NT; ++nt) {
                float2 b = *reinterpret_cast<const float2*>(sW + ((k8g * NT + nt) * 32 + lane) * 2);
                mma8(acc[nt], a, b.x, b.y);
            }
        }

        if (ch + 1 < NCH) {
            float* dst = sA + ((ch + 1) & 1) * (64 * SAPAD);
#pragma unroll
            for (int j = 0; j < 4; ++j) {
                int flat = j * NTHR + tid;
                int row = flat >> 5, kw = flat & 31;
                float4 v;
                v.x = tf32r(rn[j].x); v.y = tf32r(rn[j].y);
                v.z = tf32r(rn[j].z); v.w = tf32r(rn[j].w);
                *reinterpret_cast<float4*>(dst + row * SAPAD + kw * 4) = v;
            }
        }
        __syncthreads();
    }
}

// ---------------------------------------------------------------------------
// Persistent recurrence: 128 blocks x 512 threads; block b owns cols
// [8b, 8b+8) of ALL THREE gates. Phase A: z (nt=0) + r (nt=1); z kept in
// smem, P = r*H published. Phase B: h + H update using local z.
// ---------------------------------------------------------------------------
__global__ void __launch_bounds__(NTHR, 1)
gru_persist(const int* __restrict__ X,
            const float* __restrict__ Wz, const float* __restrict__ bz,
            const float* __restrict__ Wr, const float* __restrict__ br,
            const float* __restrict__ Wh, const float* __restrict__ bh)
{
    extern __shared__ float sm[];
    float* sWa  = sm;                  // 16384 : z|r weights (b-frag packed)
    float* sWh  = sWa + 16384;         //  8192 : h weights
    float* sA   = sWh + 8192;          // 16896 : A double buffer [2][64][SAPAD]
    float* sRed = sA + 16896;          //  4096 : K-quarter partials
    float* sZ   = sRed + 4096;         //   512 : z gate [64][8]
    int*   sXi  = reinterpret_cast<int*>(sZ + 512);  // 64 : token ids

    const int tid  = threadIdx.x;
    const int bid  = blockIdx.x;
    const int lane = tid & 31;
    const int wid  = tid >> 5;
    const int mt   = wid >> 2;
    const int kq   = wid & 3;
    const int gid  = lane >> 2;
    const int tg   = lane & 3;
    const int n0   = bid * 8;

    // pack weights -> b-fragment layout (tf32-rounded), once per launch
    for (int e = tid; e < 16384; e += NTHR) {
        int reg = e & 1, ln = (e >> 1) & 31, nt = (e >> 6) & 1, k8 = e >> 7;
        int k   = k8 * 8 + reg * 4 + (ln & 3);
        int col = n0 + (ln >> 2);
        const float* W = nt ? Wr : Wz;
        sWa[e] = tf32r(W[(size_t)(VOCAB + k) * HID + col]);
    }
    for (int e = tid; e < 8192; e += NTHR) {
        int reg = e & 1, ln = (e >> 1) & 31, k8 = e >> 6;
        int k   = k8 * 8 + reg * 4 + (ln & 3);
        int col = n0 + (ln >> 2);
        sWh[e] = tf32r(Wh[(size_t)(VOCAB + k) * HID + col]);
    }

    // zero H0: 128 x 512 = 65536 floats
    g_H[bid * NTHR + tid] = 0.f;
    gridbar();

    for (int t = 0; t < SEQ; ++t) {
        const float* Hc = g_H + (size_t)t * (BATCH * HID);
        float*       Hn = g_H + (size_t)(t + 1) * (BATCH * HID);

        if (tid < BATCH) sXi[tid] = X[tid * SEQ + t];

        // ================= Phase A: z and r for cols [n0, n0+8) =================
        {
            float acc[2][4];
            mma_phase<2>(Hc, sWa, sA, acc, tid, lane, mt, kq, gid, tg);

            if (kq != 0) {
#pragma unroll
                for (int nt = 0; nt < 2; ++nt)
                    *reinterpret_cast<float4*>(sRed + (((kq * 4 + mt) * 2 + nt) * 32 + lane) * 4) =
                        make_float4(acc[nt][0], acc[nt][1], acc[nt][2], acc[nt][3]);
            }
            __syncthreads();
            if (kq == 0) {
#pragma unroll
                for (int nt = 0; nt < 2; ++nt)
#pragma unroll
                    for (int q = 1; q < 4; ++q) {
                        float4 p = *reinterpret_cast<const float4*>(
                            sRed + (((q * 4 + mt) * 2 + nt) * 32 + lane) * 4);
                        acc[nt][0] += p.x; acc[nt][1] += p.y;
                        acc[nt][2] += p.z; acc[nt][3] += p.w;
                    }
#pragma unroll
                for (int half = 0; half < 2; ++half) {
                    int row = mt * 16 + gid + half * 8;
                    int x   = sXi[row];
                    int n   = n0 + tg * 2;
                    size_t widx = (size_t)x * HID + n;
                    int idx = row * HID + n;
                    // z -> smem (consumed by this block's phase B)
                    float2 wz2 = *reinterpret_cast<const float2*>(Wz + widx);
                    float2 bz2 = *reinterpret_cast<const float2*>(bz + n);
                    float z0 = sigmoidf_(acc[0][half * 2 + 0] + wz2.x + bz2.x);
                    float z1 = sigmoidf_(acc[0][half * 2 + 1] + wz2.y + bz2.y);
                    *reinterpret_cast<float2*>(sZ + row * 8 + tg * 2) = make_float2(z0, z1);
                    // r -> P = r * H (published globally)
                    float2 wr2 = *reinterpret_cast<const float2*>(Wr + widx);
                    float2 br2 = *reinterpret_cast<const float2*>(br + n);
                    float r0 = sigmoidf_(acc[1][half * 2 + 0] + wr2.x + br2.x);
                    float r1 = sigmoidf_(acc[1][half * 2 + 1] + wr2.y + br2.y);
                    float2 h2 = __ldcg(reinterpret_cast<const float2*>(Hc + idx));
                    __stcg(reinterpret_cast<float2*>(g_P + idx),
                           make_float2(r0 * h2.x, r1 * h2.y));
                }
            }
        }
        gridbar();

        // ================= Phase B: h gate + H update for cols [n0, n0+8) =================
        {
            float acc[1][4];
            mma_phase<1>(g_P, sWh, sA, acc, tid, lane, mt, kq, gid, tg);

            if (kq != 0) {
                *reinterpret_cast<float4*>(sRed + ((kq * 4 + mt) * 32 + lane) * 4) =
                    make_float4(acc[0][0], acc[0][1], acc[0][2], acc[0][3]);
            }
            __syncthreads();
            if (kq == 0) {
#pragma unroll
                for (int q = 1; q < 4; ++q) {
                    float4 p = *reinterpret_cast<const float4*>(
                        sRed + ((q * 4 + mt) * 32 + lane) * 4);
                    acc[0][0] += p.x; acc[0][1] += p.y;
                    acc[0][2] += p.z; acc[0][3] += p.w;
                }
#pragma unroll
                for (int half = 0; half < 2; ++half) {
                    int row = mt * 16 + gid + half * 8;
                    int x   = sXi[row];
                    int n   = n0 + tg * 2;
                    size_t widx = (size_t)x * HID + n;
                    int idx = row * HID + n;
                    float2 wh2 = *reinterpret_cast<const float2*>(Wh + widx);
                    float2 bh2 = *reinterpret_cast<const float2*>(bh + n);
                    float h0 = tanhf(acc[0][half * 2 + 0] + wh2.x + bh2.x);
                    float h1 = tanhf(acc[0][half * 2 + 1] + wh2.y + bh2.y);
                    float2 z2  = *reinterpret_cast<const float2*>(sZ + row * 8 + tg * 2);
                    float2 hc2 = __ldcg(reinterpret_cast<const float2*>(Hc + idx));
                    __stcg(reinterpret_cast<float2*>(Hn + idx),
                           make_float2(z2.x * h0 + (1.f - z2.x) * hc2.x,
                                       z2.y * h1 + (1.f - z2.y) * hc2.y));
                }
            }
        }
        gridbar();
    }
}

// ---------------------------------------------------------------------------
// Output GEMM: Y = H_all[16384 x 1024] @ Wo[1024 x 4096] + bo  (known-good)
// ---------------------------------------------------------------------------
template<int NI>
__device__ __forceinline__ void gemm_core_out(
    const float* __restrict__ A,
    const float* __restrict__ B0,
    const float* __restrict__ B1,
    int ldb, float (&acc)[2][NI][4], float* As, float* Bs)
{
    constexpr int BN = NI * 16, BSTR = BN + 8;
    const int tid = threadIdx.x, lane = tid & 31, w = tid >> 5;
    const int wm = w >> 1, wn = w & 1, gid = lane >> 2, tg = lane & 3;

#pragma unroll
    for (int mi = 0; mi < 2; ++mi)
#pragma unroll
        for (int ni = 0; ni < NI; ++ni)
#pragma unroll
            for (int e = 0; e < 4; ++e) acc[mi][ni][e] = 0.f;

    float4 ra[4]; float4 rb[NI];
#pragma unroll
    for (int j = 0; j < 4; ++j) {
        int i = tid + j * 128, row = i >> 3, kq = i & 7;
        ra[j] = *reinterpret_cast<const float4*>(A + (size_t)row * HID + kq * 4);
    }
#pragma unroll
    for (int j = 0; j < NI; ++j) {
        int i = tid + j * 128, row = i / (BN / 4), nq = i % (BN / 4), c4 = nq * 4;
        const float* src = (c4 < NI * 8) ? (B0 + (size_t)row * ldb + c4)
                                         : (B1 + (size_t)row * ldb + (c4 - NI * 8));
        rb[j] = *reinterpret_cast<const float4*>(src);
    }

    for (int kk = 0; kk < HID; kk += 32) {
#pragma unroll
        for (int j = 0; j < 4; ++j) {
            int i = tid + j * 128, row = i >> 3, kq = i & 7;
            float4 v; v.x = tf32r(ra[j].x); v.y = tf32r(ra[j].y);
            v.z = tf32r(ra[j].z); v.w = tf32r(ra[j].w);
            *reinterpret_cast<float4*>(As + row * 36 + kq * 4) = v;
        }
#pragma unroll
        for (int j = 0; j < NI; ++j) {
            int i = tid + j * 128, row = i / (BN / 4), nq = i % (BN / 4);
            float4 v; v.x = tf32r(rb[j].x); v.y = tf32r(rb[j].y);
            v.z = tf32r(rb[j].z); v.w = tf32r(rb[j].w);
            *reinterpret_cast<float4*>(Bs + row * BSTR + nq * 4) = v;
        }
        __syncthreads();
        if (kk + 32 < HID) {
#pragma unroll
            for (int j = 0; j < 4; ++j) {
                int i = tid + j * 128, row = i >> 3, kq = i & 7;
                ra[j] = *reinterpret_cast<const float4*>(A + (size_t)row * HID + kk + 32 + kq * 4);
            }
#pragma unroll
            for (int j = 0; j < NI; ++j) {
                int i = tid + j * 128, row = i / (BN / 4), nq = i % (BN / 4), c4 = nq * 4;
                const float* src = (c4 < NI * 8)
                    ? (B0 + (size_t)(kk + 32 + row) * ldb + c4)
                    : (B1 + (size_t)(kk + 32 + row) * ldb + (c4 - NI * 8));
                rb[j] = *reinterpret_cast<const float4*>(src);
            }
        }
#pragma unroll
        for (int k8 = 0; k8 < 4; ++k8) {
            int kb = k8 * 8;
            float a[2][4];
#pragma unroll
            for (int mi = 0; mi < 2; ++mi) {
                int rb0 = wm * 32 + mi * 16;
                a[mi][0] = As[(rb0 + gid) * 36 + kb + tg];
                a[mi][1] = As[(rb0 + 8 + gid) * 36 + kb + tg];
                a[mi][2] = As[(rb0 + gid) * 36 + kb + 4 + tg];
                a[mi][3] = As[(rb0 + 8 + gid) * 36 + kb + 4 + tg];
            }
#pragma unroll
            for (int ni = 0; ni < NI; ++ni) {
                int col = wn * (NI * 8) + ni * 8 + gid;
                float b0 = Bs[(kb + tg) * BSTR + col];
                float b1 = Bs[(kb + 4 + tg) * BSTR + col];
#pragma unroll
                for (int mi = 0; mi < 2; ++mi) mma8(acc[mi][ni], a[mi], b0, b1);
            }
        }
        __syncthreads();
    }
}

__global__ void __launch_bounds__(128)
gru_out(const float* __restrict__ Wo, const float* __restrict__ bo,
        float* __restrict__ out)
{
    __shared__ float As[64 * 36];
    __shared__ float Bs[32 * 72];

    const int n0 = blockIdx.x * 64;
    const int m0 = blockIdx.y * 64;
    const float* A  = g_H + (size_t)(BATCH * HID) + (size_t)m0 * HID;
    const float* B0 = Wo + n0;
    const float* B1 = Wo + n0 + 32;

    float acc[2][4][4];
    gemm_core_out<4>(A, B0, B1, VOCAB, acc, As, Bs);

    const int lane = threadIdx.x & 31, w = threadIdx.x >> 5;
    const int wm = w >> 1, wn = w & 1, gid = lane >> 2, tg = lane & 3;

#pragma unroll
    for (int mi = 0; mi < 2; ++mi)
#pragma unroll
        for (int half = 0; half < 2; ++half) {
            int row = m0 + wm * 32 + mi * 16 + half * 8 + gid;
#pragma unroll
            for (int ni = 0; ni < 4; ++ni)
#pragma unroll
                for (int e = 0; e < 2; ++e) {
                    int n = n0 + wn * 32 + ni * 8 + tg * 2 + e;
                    out[(size_t)row * VOCAB + n] = acc[mi][ni][half * 2 + e] + bo[n];
                }
        }
}

__global__ void gru_copy_hfinal(float* __restrict__ dst) {
    int i = blockIdx.x * blockDim.x + threadIdx.x;
    if (i < BATCH * HID) dst[i] = g_H[(size_t)SEQ * (BATCH * HID) + i];
}

// ---------------------------------------------------------------------------
extern "C" void kernel_launch(void* const* d_in, const int* in_sizes, int n_in,
                              void* d_out, int out_size)
{
    const int*   X  = (const int*)  d_in[0];
    const float* Wz = (const float*)d_in[1];
    const float* bz = (const float*)d_in[2];
    const float* Wr = (const float*)d_in[3];
    const float* br = (const float*)d_in[4];
    const float* Wh = (const float*)d_in[5];
    const float* bh = (const float*)d_in[6];
    const float* Wo = (const float*)d_in[7];
    const float* bo = (const float*)d_in[8];
    float* out = (float*)d_out;

    const int smemBytes = (16384 + 8192 + 16896 + 4096 + 512 + 64) * 4;  // 184576 B
    cudaFuncSetAttribute(gru_persist, cudaFuncAttributeMaxDynamicSharedMemorySize, smemBytes);

    gru_persist<<<NBLK, NTHR, smemBytes>>>(X, Wz, bz, Wr, br, Wh, bh);

    gru_out<<<dim3(VOCAB / 64, (SEQ * BATCH) / 64), 128>>>(Wo, bo, out);

    const long long ybytes = (long long)SEQ * BATCH * VOCAB;
    if ((long long)out_size >= ybytes + (long long)BATCH * HID) {
        gru_copy_hfinal<<<64, 1024>>>(out + ybytes);
    }
    (void)in_sizes; (void)n_in;
}

// round 10
// speedup vs baseline: 1.0393x; 1.0393x over previous
#include <cuda_runtime.h>
#include <cstdint>

#define BATCH  64
#define HID    1024
#define VOCAB  4096
#define SEQ    256
#define NBLK   128
#define NTHR   512
#define CH     128                 // A-chunk width (cols of K)
#define NCH    (HID / CH)          // 8 chunks
#define SAPAD  132                 // padded row stride for sA
#define NSTG   3                   // cp.async pipeline stages

// ---------------------------------------------------------------------------
// Global scratch
// ---------------------------------------------------------------------------
__device__ float g_H[(SEQ + 1) * BATCH * HID];
__device__ float g_P[BATCH * HID];
__device__ unsigned g_bar_count = 0;
__device__ unsigned g_bar_gen   = 0;

// ---------------------------------------------------------------------------
// helpers
// ---------------------------------------------------------------------------
__device__ __forceinline__ float tf32r(float x) {
    unsigned u;
    asm("cvt.rna.tf32.f32 %0, %1;" : "=r"(u) : "f"(x));
    return __uint_as_float(u);
}

__device__ __forceinline__ void mma8(float (&c)[4], const float (&a)[4], float b0, float b1) {
    unsigned a0 = __float_as_uint(a[0]), a1 = __float_as_uint(a[1]);
    unsigned a2 = __float_as_uint(a[2]), a3 = __float_as_uint(a[3]);
    unsigned B0 = __float_as_uint(b0),  B1 = __float_as_uint(b1);
    asm volatile(
        "mma.sync.aligned.m16n8k8.row.col.f32.tf32.tf32.f32 "
        "{%0,%1,%2,%3}, {%4,%5,%6,%7}, {%8,%9}, {%0,%1,%2,%3};\n"
        : "+f"(c[0]), "+f"(c[1]), "+f"(c[2]), "+f"(c[3])
        : "r"(a0), "r"(a1), "r"(a2), "r"(a3), "r"(B0), "r"(B1));
}

__device__ __forceinline__ float sigmoidf_(float x) { return 1.f / (1.f + __expf(-x)); }

__device__ __forceinline__ void cpasync16(uint32_t daddr, const float* gptr) {
    asm volatile("cp.async.cg.shared.global [%0], [%1], 16;\n"
                 :: "r"(daddr), "l"(gptr) : "memory");
}
__device__ __forceinline__ void cpasync_commit() {
    asm volatile("cp.async.commit_group;\n" ::: "memory");
}
__device__ __forceinline__ void cpasync_wait2() {
    asm volatile("cp.async.wait_group 2;\n" ::: "memory");
}

// Light release/acquire grid barrier (thread 0 only touches global).
__device__ __forceinline__ void gridbar() {
    __syncthreads();
    if (threadIdx.x == 0) {
        unsigned gen;
        asm volatile("ld.relaxed.gpu.global.u32 %0, [%1];"
                     : "=r"(gen) : "l"(&g_bar_gen) : "memory");
        unsigned old;
        asm volatile("atom.acq_rel.gpu.global.add.u32 %0, [%1], 1;"
                     : "=r"(old) : "l"(&g_bar_count) : "memory");
        if (old == NBLK - 1) {
            asm volatile("st.relaxed.gpu.global.u32 [%0], %1;"
                         :: "l"(&g_bar_count), "r"(0u) : "memory");
            asm volatile("st.release.gpu.global.u32 [%0], %1;"
                         :: "l"(&g_bar_gen), "r"(gen + 1) : "memory");
        } else {
            unsigned cur;
            do {
                asm volatile("ld.acquire.gpu.global.u32 %0, [%1];"
                             : "=r"(cur) : "l"(&g_bar_gen) : "memory");
            } while (cur == gen);
        }
    }
    __syncthreads();
}

// ---------------------------------------------------------------------------
// MMA phase with cp.async 3-stage ring:
//   acc[NT][4] = A(src)[64x1024] * W-slab(sW packed fragments)
//   wid = mt*4 + kq ; tf32 rounding applied AFTER LDS (numerics == R8).
// ---------------------------------------------------------------------------
template<int NT>
__device__ __forceinline__ void mma_phase(
    const float* __restrict__ src,
    const float* __restrict__ sW,
    float* __restrict__ sA,
    float (&acc)[NT][4],
    int tid, int lane, int mt, int kq, int gid, int tg)
{
#pragma unroll
    for (int nt = 0; nt < NT; ++nt)
#pragma unroll
        for (int e = 0; e < 4; ++e) acc[nt][e] = 0.f;

    // per-thread copy coords: 4 x 16B per chunk
    const int crow = tid >> 5;          // rows: flat>>5 with flat=j*512+tid -> row=(j*16)+(tid>>5)
    const int ckw  = tid & 31;          // float4 col within 128-col chunk

    uint32_t sbase = (uint32_t)__cvta_generic_to_shared(sA);

    // prologue: issue chunks 0..2
#pragma unroll
    for (int c = 0; c < NSTG; ++c) {
#pragma unroll
        for (int j = 0; j < 4; ++j) {
            int row = j * 16 + crow;
            uint32_t d = sbase + ((c % NSTG) * (64 * SAPAD) + row * SAPAD + ckw * 4) * 4;
            cpasync16(d, src + (size_t)row * HID + c * CH + ckw * 4);
        }
        cpasync_commit();
    }

    for (int ch = 0; ch < NCH; ++ch) {
        cpasync_wait2();          // chunk ch complete (<=2 groups pending)
        __syncthreads();          // visibility of stage ch%3 to all warps

        const float* aBase = sA + (ch % NSTG) * (64 * SAPAD) + (mt * 16 + gid) * SAPAD;
#pragma unroll
        for (int i = 0; i < 4; ++i) {
            int k8l = kq * 4 + i;
            int kb  = k8l * 8;
            float a[4];
            a[0] = tf32r(aBase[kb + tg]);
            a[1] = tf32r(aBase[8 * SAPAD + kb + tg]);
            a[2] = tf32r(aBase[kb + 4 + tg]);
            a[3] = tf32r(aBase[8 * SAPAD + kb + 4 + tg]);
            int k8g = ch * 16 + k8l;
#pragma unroll
            for (int nt = 0; nt < NT; ++nt) {
                float2 b = *reinterpret_cast<const float2*>(sW + ((k8g * NT + nt) * 32 + lane) * 2);
                mma8(acc[nt], a, b.x, b.y);
            }
        }
        __syncthreads();          // all consumers done with stage ch%3

        if (ch + NSTG < NCH) {    // refill the stage we just consumed
            int c = ch + NSTG;
#pragma unroll
            for (int j = 0; j < 4; ++j) {
                int row = j * 16 + crow;
                uint32_t d = sbase + ((c % NSTG) * (64 * SAPAD) + row * SAPAD + ckw * 4) * 4;
                cpasync16(d, src + (size_t)row * HID + c * CH + ckw * 4);
            }
            cpasync_commit();
        }
    }
}

// ---------------------------------------------------------------------------
// Persistent recurrence: 128 blocks x 512 threads; block b owns cols
// [8b, 8b+8) of ALL THREE gates. Phase A: z + r (z kept in smem, P=r*H
// published). Phase B: h + H update using local z.
// ---------------------------------------------------------------------------
__global__ void __launch_bounds__(NTHR, 1)
gru_persist(const int* __restrict__ X,
            const float* __restrict__ Wz, const float* __restrict__ bz,
            const float* __restrict__ Wr, const float* __restrict__ br,
            const float* __restrict__ Wh, const float* __restrict__ bh)
{
    extern __shared__ float sm[];
    float* sWa  = sm;                        // 16384 : z|r weights (b-frag packed)
    float* sWh  = sWa + 16384;               //  8192 : h weights
    float* sA   = sWh + 8192;                // 25344 : A ring [3][64][SAPAD]
    float* sRed = sA + NSTG * 64 * SAPAD;    //  4096 : K-quarter partials
    float* sZ   = sRed + 4096;               //   512 : z gate [64][8]
    int*   sXi  = reinterpret_cast<int*>(sZ + 512);  // 64 token ids

    const int tid  = threadIdx.x;
    const int bid  = blockIdx.x;
    const int lane = tid & 31;
    const int wid  = tid >> 5;
    const int mt   = wid >> 2;
    const int kq   = wid & 3;
    const int gid  = lane >> 2;
    const int tg   = lane & 3;
    const int n0   = bid * 8;

    // pack weights -> b-fragment layout (tf32-rounded), once per launch
    for (int e = tid; e < 16384; e += NTHR) {
        int reg = e & 1, ln = (e >> 1) & 31, nt = (e >> 6) & 1, k8 = e >> 7;
        int k   = k8 * 8 + reg * 4 + (ln & 3);
        int col = n0 + (ln >> 2);
        const float* W = nt ? Wr : Wz;
        sWa[e] = tf32r(W[(size_t)(VOCAB + k) * HID + col]);
    }
    for (int e = tid; e < 8192; e += NTHR) {
        int reg = e & 1, ln = (e >> 1) & 31, k8 = e >> 6;
        int k   = k8 * 8 + reg * 4 + (ln & 3);
        int col = n0 + (ln >> 2);
        sWh[e] = tf32r(Wh[(size_t)(VOCAB + k) * HID + col]);
    }

    // zero H0: 128 x 512 = 65536 floats
    g_H[bid * NTHR + tid] = 0.f;
    gridbar();

    for (int t = 0; t < SEQ; ++t) {
        const float* Hc = g_H + (size_t)t * (BATCH * HID);
        float*       Hn = g_H + (size_t)(t + 1) * (BATCH * HID);

        if (tid < BATCH) sXi[tid] = X[tid * SEQ + t];

        // ================= Phase A: z and r for cols [n0, n0+8) =================
        {
            float acc[2][4];
            mma_phase<2>(Hc, sWa, sA, acc, tid, lane, mt, kq, gid, tg);

            if (kq != 0) {
#pragma unroll
                for (int nt = 0; nt < 2; ++nt)
                    *reinterpret_cast<float4*>(sRed + (((kq * 4 + mt) * 2 + nt) * 32 + lane) * 4) =
                        make_float4(acc[nt][0], acc[nt][1], acc[nt][2], acc[nt][3]);
            }
            __syncthreads();
            if (kq == 0) {
#pragma unroll
                for (int nt = 0; nt < 2; ++nt)
#pragma unroll
                    for (int q = 1; q < 4; ++q) {
                        float4 p = *reinterpret_cast<const float4*>(
                            sRed + (((q * 4 + mt) * 2 + nt) * 32 + lane) * 4);
                        acc[nt][0] += p.x; acc[nt][1] += p.y;
                        acc[nt][2] += p.z; acc[nt][3] += p.w;
                    }
#pragma unroll
                for (int half = 0; half < 2; ++half) {
                    int row = mt * 16 + gid + half * 8;
                    int x   = sXi[row];
                    int n   = n0 + tg * 2;
                    size_t widx = (size_t)x * HID + n;
                    int idx = row * HID + n;
                    float2 wz2 = *reinterpret_cast<const float2*>(Wz + widx);
                    float2 bz2 = *reinterpret_cast<const float2*>(bz + n);
                    float z0 = sigmoidf_(acc[0][half * 2 + 0] + wz2.x + bz2.x);
                    float z1 = sigmoidf_(acc[0][half * 2 + 1] + wz2.y + bz2.y);
                    *reinterpret_cast<float2*>(sZ + row * 8 + tg * 2) = make_float2(z0, z1);
                    float2 wr2 = *reinterpret_cast<const float2*>(Wr + widx);
                    float2 br2 = *reinterpret_cast<const float2*>(br + n);
                    float r0 = sigmoidf_(acc[1][half * 2 + 0] + wr2.x + br2.x);
                    float r1 = sigmoidf_(acc[1][half * 2 + 1] + wr2.y + br2.y);
                    float2 h2 = __ldcg(reinterpret_cast<const float2*>(Hc + idx));
                    __stcg(reinterpret_cast<float2*>(g_P + idx),
                           make_float2(r0 * h2.x, r1 * h2.y));
                }
            }
        }
        gridbar();

        // ================= Phase B: h gate + H update =================
        {
            float acc[1][4];
            mma_phase<1>(g_P, sWh, sA, acc, tid, lane, mt, kq, gid, tg);

            if (kq != 0) {
                *reinterpret_cast<float4*>(sRed + ((kq * 4 + mt) * 32 + lane) * 4) =
                    make_float4(acc[0][0], acc[0][1], acc[0][2], acc[0][3]);
            }
            __syncthreads();
            if (kq == 0) {
#pragma unroll
                for (int q = 1; q < 4; ++q) {
                    float4 p = *reinterpret_cast<const float4*>(
                        sRed + ((q * 4 + mt) * 32 + lane) * 4);
                    acc[0][0] += p.x; acc[0][1] += p.y;
                    acc[0][2] += p.z; acc[0][3] += p.w;
                }
#pragma unroll
                for (int half = 0; half < 2; ++half) {
                    int row = mt * 16 + gid + half * 8;
                    int x   = sXi[row];
                    int n   = n0 + tg * 2;
                    size_t widx = (size_t)x * HID + n;
                    int idx = row * HID + n;
                    float2 wh2 = *reinterpret_cast<const float2*>(Wh + widx);
                    float2 bh2 = *reinterpret_cast<const float2*>(bh + n);
                    float h0 = tanhf(acc[0][half * 2 + 0] + wh2.x + bh2.x);
                    float h1 = tanhf(acc[0][half * 2 + 1] + wh2.y + bh2.y);
                    float2 z2  = *reinterpret_cast<const float2*>(sZ + row * 8 + tg * 2);
                    float2 hc2 = __ldcg(reinterpret_cast<const float2*>(Hc + idx));
                    __stcg(reinterpret_cast<float2*>(Hn + idx),
                           make_float2(z2.x * h0 + (1.f - z2.x) * hc2.x,
                                       z2.y * h1 + (1.f - z2.y) * hc2.y));
                }
            }
        }
        gridbar();
    }
}

// ---------------------------------------------------------------------------
// Output GEMM v2: Y = H_all[16384 x 1024] @ Wo[1024 x 4096] + bo
//   128x64 block tile, 256 threads (8 warps: 4 m-rows x 2 n-cols).
//   Halves Wo re-reads vs the 64x64 version (L2-traffic bound kernel).
// ---------------------------------------------------------------------------
__global__ void __launch_bounds__(256)
gru_out2(const float* __restrict__ Wo, const float* __restrict__ bo,
         float* __restrict__ out)
{
    __shared__ float As[128 * 36];
    __shared__ float Bs[32 * 72];

    const int n0 = blockIdx.x * 64;
    const int m0 = blockIdx.y * 128;
    const float* A  = g_H + (size_t)(BATCH * HID) + (size_t)m0 * HID;
    const float* B0 = Wo + n0;
    const float* B1 = Wo + n0 + 32;

    const int tid = threadIdx.x, lane = tid & 31, w = tid >> 5;
    const int wm = w >> 1, wn = w & 1, gid = lane >> 2, tg = lane & 3;

    float acc[2][4][4];
#pragma unroll
    for (int mi = 0; mi < 2; ++mi)
#pragma unroll
        for (int ni = 0; ni < 4; ++ni)
#pragma unroll
            for (int e = 0; e < 4; ++e) acc[mi][ni][e] = 0.f;

    float4 ra[4]; float4 rb[2];
#pragma unroll
    for (int j = 0; j < 4; ++j) {
        int i = tid + j * 256, row = i >> 3, kq8 = i & 7;
        ra[j] = *reinterpret_cast<const float4*>(A + (size_t)row * HID + kq8 * 4);
    }
#pragma unroll
    for (int j = 0; j < 2; ++j) {
        int i = tid + j * 256, row = i >> 4, nq = i & 15, c4 = nq * 4;
        const float* src = (c4 < 32) ? (B0 + (size_t)row * VOCAB + c4)
                                     : (B1 + (size_t)row * VOCAB + (c4 - 32));
        rb[j] = *reinterpret_cast<const float4*>(src);
    }

    for (int kk = 0; kk < HID; kk += 32) {
#pragma unroll
        for (int j = 0; j < 4; ++j) {
            int i = tid + j * 256, row = i >> 3, kq8 = i & 7;
            float4 v; v.x = tf32r(ra[j].x); v.y = tf32r(ra[j].y);
            v.z = tf32r(ra[j].z); v.w = tf32r(ra[j].w);
            *reinterpret_cast<float4*>(As + row * 36 + kq8 * 4) = v;
        }
#pragma unroll
        for (int j = 0; j < 2; ++j) {
            int i = tid + j * 256, row = i >> 4, nq = i & 15;
            float4 v; v.x = tf32r(rb[j].x); v.y = tf32r(rb[j].y);
            v.z = tf32r(rb[j].z); v.w = tf32r(rb[j].w);
            *reinterpret_cast<float4*>(Bs + row * 72 + nq * 4) = v;
        }
        __syncthreads();
        if (kk + 32 < HID) {
#pragma unroll
            for (int j = 0; j < 4; ++j) {
                int i = tid + j * 256, row = i >> 3, kq8 = i & 7;
                ra[j] = *reinterpret_cast<const float4*>(A + (size_t)row * HID + kk + 32 + kq8 * 4);
            }
#pragma unroll
            for (int j = 0; j < 2; ++j) {
                int i = tid + j * 256, row = i >> 4, nq = i & 15, c4 = nq * 4;
                const float* src = (c4 < 32)
                    ? (B0 + (size_t)(kk + 32 + row) * VOCAB + c4)
                    : (B1 + (size_t)(kk + 32 + row) * VOCAB + (c4 - 32));
                rb[j] = *reinterpret_cast<const float4*>(src);
            }
        }
#pragma unroll
        for (int k8 = 0; k8 < 4; ++k8) {
            int kb = k8 * 8;
            float a[2][4];
#pragma unroll
            for (int mi = 0; mi < 2; ++mi) {
                int rb0 = wm * 32 + mi * 16;
                a[mi][0] = As[(rb0 + gid) * 36 + kb + tg];
                a[mi][1] = As[(rb0 + 8 + gid) * 36 + kb + tg];
                a[mi][2] = As[(rb0 + gid) * 36 + kb + 4 + tg];
                a[mi][3] = As[(rb0 + 8 + gid) * 36 + kb + 4 + tg];
            }
#pragma unroll
            for (int ni = 0; ni < 4; ++ni) {
                int col = wn * 32 + ni * 8 + gid;
                float b0 = Bs[(kb + tg) * 72 + col];
                float b1 = Bs[(kb + 4 + tg) * 72 + col];
#pragma unroll
                for (int mi = 0; mi < 2; ++mi) mma8(acc[mi][ni], a[mi], b0, b1);
            }
        }
        __syncthreads();
    }

#pragma unroll
    for (int mi = 0; mi < 2; ++mi)
#pragma unroll
        for (int half = 0; half < 2; ++half) {
            int row = m0 + wm * 32 + mi * 16 + half * 8 + gid;
#pragma unroll
            for (int ni = 0; ni < 4; ++ni)
#pragma unroll
                for (int e = 0; e < 2; ++e) {
                    int n = n0 + wn * 32 + ni * 8 + tg * 2 + e;
                    out[(size_t)row * VOCAB + n] = acc[mi][ni][half * 2 + e] + bo[n];
                }
        }
}

__global__ void gru_copy_hfinal(float* __restrict__ dst) {
    int i = blockIdx.x * blockDim.x + threadIdx.x;
    if (i < BATCH * HID) dst[i] = g_H[(size_t)SEQ * (BATCH * HID) + i];
}

// ---------------------------------------------------------------------------
extern "C" void kernel_launch(void* const* d_in, const int* in_sizes, int n_in,
                              void* d_out, int out_size)
{
    const int*   X  = (const int*)  d_in[0];
    const float* Wz = (const float*)d_in[1];
    const float* bz = (const float*)d_in[2];
    const float* Wr = (const float*)d_in[3];
    const float* br = (const float*)d_in[4];
    const float* Wh = (const float*)d_in[5];
    const float* bh = (const float*)d_in[6];
    const float* Wo = (const float*)d_in[7];
    const float* bo = (const float*)d_in[8];
    float* out = (float*)d_out;

    const int smemFloats = 16384 + 8192 + NSTG * 64 * SAPAD + 4096 + 512 + 64;
    const int smemBytes  = smemFloats * 4;   // 218368 B
    cudaFuncSetAttribute(gru_persist, cudaFuncAttributeMaxDynamicSharedMemorySize, smemBytes);

    gru_persist<<<NBLK, NTHR, smemBytes>>>(X, Wz, bz, Wr, br, Wh, bh);

    gru_out2<<<dim3(VOCAB / 64, (SEQ * BATCH) / 128), 256>>>(Wo, bo, out);

    const long long ybytes = (long long)SEQ * BATCH * VOCAB;
    if ((long long)out_size >= ybytes + (long long)BATCH * HID) {
        gru_copy_hfinal<<<64, 1024>>>(out + ybytes);
    }
    (void)in_sizes; (void)n_in;
}